// round 6
// baseline (speedup 1.0000x reference)
#include <cuda_runtime.h>
#include <cstdint>

#define B_  4
#define T_  512
#define G_  129
#define F_  96
#define O_  96

#define MT  256
#define XROWS (MT + 2)                 // 258
#define XSTRIDE 104                    // floats; 96 data + 8 pad (104 mod 32 = 8 -> conflict-free LDS.64)
#define XS_FLOATS (XROWS * XSTRIDE)    // 26832

// B layout: per (kk,ks) block of 768 floats:
//   [plane b0: 32 slots x 12 floats][plane b1: 32 slots x 12 floats]
// slot == lane; within slot, n-order = {0,1,2,3, 6,7,8,9, 4,5, 10,11}
#define WBLK 768
#define WS_FLOATS (36 * WBLK)          // 27648
#define SMEM_BYTES ((WS_FLOATS + XS_FLOATS) * 4)   // 217,920 B

__device__ __forceinline__ float f2tf32f(float f) {
    uint32_t r;
    asm("cvt.rna.tf32.f32 %0, %1;" : "=r"(r) : "f"(f));
    return __uint_as_float(r);
}

__device__ __forceinline__ void mma_tf32(float c[4], float a0, float a1, float a2, float a3,
                                         float b0, float b1) {
    asm volatile(
        "mma.sync.aligned.m16n8k8.row.col.f32.tf32.tf32.f32 "
        "{%0,%1,%2,%3}, {%4,%5,%6,%7}, {%8,%9}, {%0,%1,%2,%3};"
        : "+f"(c[0]), "+f"(c[1]), "+f"(c[2]), "+f"(c[3])
        : "r"(__float_as_uint(a0)), "r"(__float_as_uint(a1)),
          "r"(__float_as_uint(a2)), "r"(__float_as_uint(a3)),
          "r"(__float_as_uint(b0)), "r"(__float_as_uint(b1)));
}

__global__ __launch_bounds__(256, 1)
void conv1d_mma_kernel(const float* __restrict__ x,
                       const float* __restrict__ w,
                       const float* __restrict__ bias,
                       float* __restrict__ out)
{
    extern __shared__ float sm[];
    float* ws = sm;                 // 27648 floats
    float* xs = sm + WS_FLOATS;     // 26832 floats

    const int tid = threadIdx.x, wid = tid >> 5, lane = tid & 31;
    const int wm = wid & 3, wn = wid >> 2;     // 4 M-warps x 2 N-warps
    const int lane4 = lane >> 2, lc = lane & 3;
    const int g   = blockIdx.y;
    const int m0  = blockIdx.x * MT;
    const int b   = m0 >> 9;
    const int tl0 = m0 & 511;

    // ---- W[g] -> smem (tf32, slot layout)
    {
        const float4* wg4 = (const float4*)(w + (size_t)g * (O_ * F_ * 3));
        for (int q = tid; q < (O_ * F_ * 3) / 4; q += 256) {
            float4 v = wg4[q];
            int e = q * 4;
            int o = e / (F_ * 3);
            int rem = e - o * (F_ * 3);          // o fixed across the 4 (288 % 4 == 0)
            int n = o >> 3, nsub = o & 7;
            int slot12 = (nsub * 4 /*krow added below*/) * 12;  // partial
            int pos = (n < 4) ? n : (n < 6 ? n + 4 : (n < 10 ? n - 2 : n));
            const float* vf = (const float*)&v;
            #pragma unroll
            for (int j = 0; j < 4; ++j) {
                int rr = rem + j;
                int f = rr / 3, kk = rr - 3 * f;
                int ks = f >> 3, fp = f & 7;
                int plane = fp >> 2, krow = fp & 3;
                ws[(kk * 12 + ks) * WBLK + plane * 384 + slot12 + krow * 12 + pos] = f2tf32f(vf[j]);
            }
        }
    }

    // ---- x tile -> smem: row p, layout [p][ks(12)][c(4) as float2 (v_c, v_{c+4})]
    {
        const float* xg = x + (((size_t)b * T_) * G_ + g) * F_;
        for (int q = tid; q < XROWS * 12; q += 256) {
            int p = q / 12, ksq = q - p * 12;
            int t = tl0 - 1 + p;
            float4 lo = make_float4(0.f, 0.f, 0.f, 0.f), hi = lo;
            if (t >= 0 && t < T_) {
                const float* src = xg + (size_t)t * (G_ * F_) + ksq * 8;
                lo = *(const float4*)(src);
                hi = *(const float4*)(src + 4);
            }
            float* dst = xs + p * XSTRIDE + ksq * 8;
            *(float4*)(dst)     = make_float4(f2tf32f(lo.x), f2tf32f(hi.x), f2tf32f(lo.y), f2tf32f(hi.y));
            *(float4*)(dst + 4) = make_float4(f2tf32f(lo.z), f2tf32f(hi.z), f2tf32f(lo.w), f2tf32f(hi.w));
        }
    }
    __syncthreads();

    // ---- accumulators pre-loaded with bias
    float acc[4][6][4];
    {
        const float* bg = bias + g * O_ + wn * 48 + 2 * lc;
        #pragma unroll
        for (int jn = 0; jn < 6; ++jn) {
            float b0v = bg[jn * 8], b1v = bg[jn * 8 + 1];
            #pragma unroll
            for (int mb = 0; mb < 4; ++mb) {
                acc[mb][jn][0] = b0v; acc[mb][jn][1] = b1v;
                acc[mb][jn][2] = b0v; acc[mb][jn][3] = b1v;
            }
        }
    }

    // ---- main loop
    const float* paw = xs + (wm * 64 + lane4) * XSTRIDE + lc * 2;   // A base (rows m, pair c)
    const float* pbl = ws + lane * 12;                              // B slot base

    #pragma unroll
    for (int kk = 0; kk < 3; ++kk) {
        const float* pa = paw + kk * XSTRIDE;
        const float* pb = pbl + kk * 12 * WBLK;
        #pragma unroll 4
        for (int ks = 0; ks < 12; ++ks) {
            // B fragments: 6 n-blocks for this N-warp
            const float* pbs = pb + ks * WBLK;
            float4 b0lo = *(const float4*)(pbs + wn * 4);
            float2 b0hi = *(const float2*)(pbs + 8 + wn * 2);
            float4 b1lo = *(const float4*)(pbs + 384 + wn * 4);
            float2 b1hi = *(const float2*)(pbs + 384 + 8 + wn * 2);
            float b0f[6] = { b0lo.x, b0lo.y, b0lo.z, b0lo.w, b0hi.x, b0hi.y };
            float b1f[6] = { b1lo.x, b1lo.y, b1lo.z, b1lo.w, b1hi.x, b1hi.y };

            // A fragments: 4 m-blocks (rows wm*64 + mb*16 + lane4 (+8), cols lc (+4))
            float2 alo[4], ahi[4];
            #pragma unroll
            for (int mb = 0; mb < 4; ++mb) {
                const float* pam = pa + mb * 16 * XSTRIDE + ks * 8;
                alo[mb] = *(const float2*)(pam);                 // (a0, a2)
                ahi[mb] = *(const float2*)(pam + 8 * XSTRIDE);   // (a1, a3)
            }

            #pragma unroll
            for (int mb = 0; mb < 4; ++mb) {
                #pragma unroll
                for (int jn = 0; jn < 6; ++jn)
                    mma_tf32(acc[mb][jn], alo[mb].x, ahi[mb].x, alo[mb].y, ahi[mb].y,
                             b0f[jn], b1f[jn]);
            }
        }
    }

    // ---- store
    const int colb = wn * 48 + 2 * lc;
    #pragma unroll
    for (int mb = 0; mb < 4; ++mb) {
        int rbase = m0 + wm * 64 + mb * 16 + lane4;
        #pragma unroll
        for (int h = 0; h < 2; ++h) {
            size_t gm = (size_t)(rbase + h * 8);
            float* op = out + (gm * G_ + g) * O_ + colb;
            #pragma unroll
            for (int jn = 0; jn < 6; ++jn)
                *(float2*)(op + jn * 8) = make_float2(acc[mb][jn][2 * h], acc[mb][jn][2 * h + 1]);
        }
    }
}

extern "C" void kernel_launch(void* const* d_in, const int* in_sizes, int n_in,
                              void* d_out, int out_size)
{
    const float* x    = (const float*)d_in[0];
    const float* wgt  = (const float*)d_in[1];
    const float* bias = (const float*)d_in[2];
    float* out        = (float*)d_out;

    cudaFuncSetAttribute(conv1d_mma_kernel,
                         cudaFuncAttributeMaxDynamicSharedMemorySize, SMEM_BYTES);

    dim3 grid((B_ * T_) / MT, G_);   // 8 x 129 = 1032 CTAs
    conv1d_mma_kernel<<<grid, 256, SMEM_BYTES>>>(x, wgt, bias, out);
}

// round 8
// speedup vs baseline: 1.4108x; 1.4108x over previous
#include <cuda_runtime.h>
#include <cstdint>

#define B_  4
#define T_  512
#define G_  129
#define F_  96
#define O_  96

#define MT  256
#define XROWS (MT + 2)                 // 258
#define XSTRIDE 104                    // 96 data + 8 pad (104 mod 32 = 8 -> conflict-free LDS.64)
#define XS_FLOATS (XROWS * XSTRIDE)    // 26832

// B layout: per (kk,ks) block of 768 floats:
//   [plane b0: 32 slots x 12 floats][plane b1: 32 slots x 12 floats]
// slot == lane; within slot, n-order = {0,1,2,3, 6,7,8,9, 4,5, 10,11}
#define WBLK 768
#define WS_FLOATS (36 * WBLK)          // 27648
#define SMEM_BYTES ((WS_FLOATS + XS_FLOATS) * 4)   // 217,920 B

#define NTHREADS 512

__device__ __forceinline__ float f2tf32f(float f) {
    uint32_t r;
    asm("cvt.rna.tf32.f32 %0, %1;" : "=r"(r) : "f"(f));
    return __uint_as_float(r);
}

__device__ __forceinline__ void mma_tf32(float c[4], float a0, float a1, float a2, float a3,
                                         float b0, float b1) {
    asm volatile(
        "mma.sync.aligned.m16n8k8.row.col.f32.tf32.tf32.f32 "
        "{%0,%1,%2,%3}, {%4,%5,%6,%7}, {%8,%9}, {%0,%1,%2,%3};"
        : "+f"(c[0]), "+f"(c[1]), "+f"(c[2]), "+f"(c[3])
        : "r"(__float_as_uint(a0)), "r"(__float_as_uint(a1)),
          "r"(__float_as_uint(a2)), "r"(__float_as_uint(a3)),
          "r"(__float_as_uint(b0)), "r"(__float_as_uint(b1)));
}

__global__ __launch_bounds__(NTHREADS, 1)
void conv1d_mma_kernel(const float* __restrict__ x,
                       const float* __restrict__ w,
                       const float* __restrict__ bias,
                       float* __restrict__ out)
{
    extern __shared__ float sm[];
    float* ws = sm;                 // 27648 floats
    float* xs = sm + WS_FLOATS;     // 26832 floats

    const int tid = threadIdx.x, wid = tid >> 5, lane = tid & 31;
    const int wm = wid & 7, wn = wid >> 3;     // 8 M-warps x 2 N-warps
    const int lane4 = lane >> 2, lc = lane & 3;
    const int g   = blockIdx.y;
    const int m0  = blockIdx.x * MT;
    const int b   = m0 >> 9;
    const int tl0 = m0 & 511;

    // ---- W[g] -> smem (tf32, slot layout)
    {
        const float4* wg4 = (const float4*)(w + (size_t)g * (O_ * F_ * 3));
        for (int q = tid; q < (O_ * F_ * 3) / 4; q += NTHREADS) {
            float4 v = wg4[q];
            int e = q * 4;
            int o = e / (F_ * 3);
            int rem = e - o * (F_ * 3);          // o fixed across the 4 (288 % 4 == 0)
            int n = o >> 3, nsub = o & 7;
            int slot12 = (nsub * 4) * 12;
            int pos = (n < 4) ? n : (n < 6 ? n + 4 : (n < 10 ? n - 2 : n));
            const float* vf = (const float*)&v;
            #pragma unroll
            for (int j = 0; j < 4; ++j) {
                int rr = rem + j;
                int f = rr / 3, kk = rr - 3 * f;
                int ks = f >> 3, fp = f & 7;
                int plane = fp >> 2, krow = fp & 3;
                ws[(kk * 12 + ks) * WBLK + plane * 384 + slot12 + krow * 12 + pos] = f2tf32f(vf[j]);
            }
        }
    }

    // ---- x tile -> smem: row p, layout [p][ks(12)][c(4) as float2 (v_c, v_{c+4})]
    {
        const float* xg = x + (((size_t)b * T_) * G_ + g) * F_;
        for (int q = tid; q < XROWS * 12; q += NTHREADS) {
            int p = q / 12, ksq = q - p * 12;
            int t = tl0 - 1 + p;
            float4 lo = make_float4(0.f, 0.f, 0.f, 0.f), hi = lo;
            if (t >= 0 && t < T_) {
                const float* src = xg + (size_t)t * (G_ * F_) + ksq * 8;
                lo = *(const float4*)(src);
                hi = *(const float4*)(src + 4);
            }
            float* dst = xs + p * XSTRIDE + ksq * 8;
            *(float4*)(dst)     = make_float4(f2tf32f(lo.x), f2tf32f(hi.x), f2tf32f(lo.y), f2tf32f(hi.y));
            *(float4*)(dst + 4) = make_float4(f2tf32f(lo.z), f2tf32f(hi.z), f2tf32f(lo.w), f2tf32f(hi.w));
        }
    }
    __syncthreads();

    // ---- accumulators pre-loaded with bias
    float acc[2][6][4];
    {
        const float* bg = bias + g * O_ + wn * 48 + 2 * lc;
        #pragma unroll
        for (int jn = 0; jn < 6; ++jn) {
            float b0v = bg[jn * 8], b1v = bg[jn * 8 + 1];
            #pragma unroll
            for (int mb = 0; mb < 2; ++mb) {
                acc[mb][jn][0] = b0v; acc[mb][jn][1] = b1v;
                acc[mb][jn][2] = b0v; acc[mb][jn][3] = b1v;
            }
        }
    }

    // ---- main loop: warp tile m32 x n48, fully unrolled 36 steps
    const float* paw = xs + (wm * 32 + lane4) * XSTRIDE + lc * 2;
    const float* pbl = ws + lane * 12;

    #pragma unroll
    for (int kk = 0; kk < 3; ++kk) {
        #pragma unroll
        for (int ks = 0; ks < 12; ++ks) {
            const float* pbs = pbl + (kk * 12 + ks) * WBLK;
            float4 b0lo = *(const float4*)(pbs + wn * 4);
            float2 b0hi = *(const float2*)(pbs + 8 + wn * 2);
            float4 b1lo = *(const float4*)(pbs + 384 + wn * 4);
            float2 b1hi = *(const float2*)(pbs + 384 + 8 + wn * 2);
            float b0f[6] = { b0lo.x, b0lo.y, b0lo.z, b0lo.w, b0hi.x, b0hi.y };
            float b1f[6] = { b1lo.x, b1lo.y, b1lo.z, b1lo.w, b1hi.x, b1hi.y };

            const float* pam = paw + kk * XSTRIDE + ks * 8;
            float2 alo0 = *(const float2*)(pam);
            float2 ahi0 = *(const float2*)(pam + 8 * XSTRIDE);
            float2 alo1 = *(const float2*)(pam + 16 * XSTRIDE);
            float2 ahi1 = *(const float2*)(pam + 24 * XSTRIDE);

            #pragma unroll
            for (int jn = 0; jn < 6; ++jn) {
                mma_tf32(acc[0][jn], alo0.x, ahi0.x, alo0.y, ahi0.y, b0f[jn], b1f[jn]);
                mma_tf32(acc[1][jn], alo1.x, ahi1.x, alo1.y, ahi1.y, b0f[jn], b1f[jn]);
            }
        }
    }

    // ---- store
    const int colb = wn * 48 + 2 * lc;
    #pragma unroll
    for (int mb = 0; mb < 2; ++mb) {
        int rbase = m0 + wm * 32 + mb * 16 + lane4;
        #pragma unroll
        for (int h = 0; h < 2; ++h) {
            size_t gm = (size_t)(rbase + h * 8);
            float* op = out + (gm * G_ + g) * O_ + colb;
            #pragma unroll
            for (int jn = 0; jn < 6; ++jn)
                *(float2*)(op + jn * 8) = make_float2(acc[mb][jn][2 * h], acc[mb][jn][2 * h + 1]);
        }
    }
}

extern "C" void kernel_launch(void* const* d_in, const int* in_sizes, int n_in,
                              void* d_out, int out_size)
{
    const float* x    = (const float*)d_in[0];
    const float* wgt  = (const float*)d_in[1];
    const float* bias = (const float*)d_in[2];
    float* out        = (float*)d_out;

    cudaFuncSetAttribute(conv1d_mma_kernel,
                         cudaFuncAttributeMaxDynamicSharedMemorySize, SMEM_BYTES);

    dim3 grid((B_ * T_) / MT, G_);   // 8 x 129 = 1032 CTAs
    conv1d_mma_kernel<<<grid, NTHREADS, SMEM_BYTES>>>(x, wgt, bias, out);
}

// round 9
// speedup vs baseline: 1.6269x; 1.1531x over previous
#include <cuda_runtime.h>
#include <cstdint>

#define B_  4
#define T_  512
#define G_  129
#define F_  96
#define O_  96

#define MT  256
#define XROWS (MT + 2)                 // 258
#define XSTRIDE 104                    // 96 data + 8 pad (104 mod 32 = 8 -> conflict-free LDS.64)
#define XS_FLOATS (XROWS * XSTRIDE)    // 26832

// B layout: per (kk,ks) block of 768 floats:
//   [plane b0: 32 slots x 12 floats][plane b1: 32 slots x 12 floats]
// slot == nsub*4+krow (== lane in mainloop); within slot, n-order = {0,1,2,3, 6,7,8,9, 4,5, 10,11}
#define WBLK 768
#define WS_FLOATS (36 * WBLK)          // 27648
#define SMEM_BYTES ((WS_FLOATS + XS_FLOATS) * 4)   // 217,920 B

#define NTHREADS 512

// Reformatted weights: [G][6912] float4 (tf32 bits, slot layout), static global scratch.
__device__ float4 d_wfmt[G_ * (WS_FLOATS / 4)];

__device__ __forceinline__ float f2tf32f(float f) {
    uint32_t r;
    asm("cvt.rna.tf32.f32 %0, %1;" : "=r"(r) : "f"(f));
    return __uint_as_float(r);
}

__device__ __forceinline__ void cp_async16(uint32_t saddr, const void* gptr) {
    asm volatile("cp.async.cg.shared.global [%0], [%1], 16;" :: "r"(saddr), "l"(gptr));
}
__device__ __forceinline__ uint32_t smem_u32(const void* p) {
    uint32_t a;
    asm("{ .reg .u64 t; cvta.to.shared.u64 t, %1; cvt.u32.u64 %0, t; }" : "=r"(a) : "l"(p));
    return a;
}

__device__ __forceinline__ void mma_tf32(float c[4], float a0, float a1, float a2, float a3,
                                         float b0, float b1) {
    asm volatile(
        "mma.sync.aligned.m16n8k8.row.col.f32.tf32.tf32.f32 "
        "{%0,%1,%2,%3}, {%4,%5,%6,%7}, {%8,%9}, {%0,%1,%2,%3};"
        : "+f"(c[0]), "+f"(c[1]), "+f"(c[2]), "+f"(c[3])
        : "r"(__float_as_uint(a0)), "r"(__float_as_uint(a1)),
          "r"(__float_as_uint(a2)), "r"(__float_as_uint(a3)),
          "r"(__float_as_uint(b0)), "r"(__float_as_uint(b1)));
}

// ---- Kernel A: per-group weight reformat (scatter once per g, coalesced writeback)
__global__ __launch_bounds__(256, 1)
void w_reformat_kernel(const float* __restrict__ w)
{
    extern __shared__ float ws[];          // 27648 floats
    const int tid = threadIdx.x;
    const int g = blockIdx.x;

    const float4* wg4 = (const float4*)(w + (size_t)g * (O_ * F_ * 3));
    for (int q = tid; q < (O_ * F_ * 3) / 4; q += 256) {
        float4 v = wg4[q];
        int e = q * 4;
        int o = e / (F_ * 3);
        int rem = e - o * (F_ * 3);          // o fixed across the 4 (288 % 4 == 0)
        int n = o >> 3, nsub = o & 7;
        int slot12 = (nsub * 4) * 12;
        int pos = (n < 4) ? n : (n < 6 ? n + 4 : (n < 10 ? n - 2 : n));
        const float* vf = (const float*)&v;
        #pragma unroll
        for (int j = 0; j < 4; ++j) {
            int rr = rem + j;
            int f = rr / 3, kk = rr - 3 * f;
            int ks = f >> 3, fp = f & 7;
            int plane = fp >> 2, krow = fp & 3;
            ws[(kk * 12 + ks) * WBLK + plane * 384 + slot12 + krow * 12 + pos] = f2tf32f(vf[j]);
        }
    }
    __syncthreads();

    float4* dst = d_wfmt + (size_t)g * (WS_FLOATS / 4);
    for (int q = tid; q < WS_FLOATS / 4; q += 256)
        dst[q] = *(const float4*)(ws + q * 4);
}

// ---- Kernel B: main GEMM-conv
__global__ __launch_bounds__(NTHREADS, 1)
void conv1d_mma_kernel(const float* __restrict__ x,
                       const float* __restrict__ bias,
                       float* __restrict__ out)
{
    extern __shared__ float sm[];
    float* ws = sm;                 // 27648 floats
    float* xs = sm + WS_FLOATS;     // 26832 floats

    const int tid = threadIdx.x, wid = tid >> 5, lane = tid & 31;
    const int wm = wid & 7, wn = wid >> 3;     // 8 M-warps x 2 N-warps
    const int lane4 = lane >> 2, lc = lane & 3;
    const int g   = blockIdx.y;
    const int m0  = blockIdx.x * MT;
    const int b   = m0 >> 9;
    const int tl0 = m0 & 511;

    // ---- W[g]: straight async copy from the reformatted buffer
    {
        const uint32_t ws_s = smem_u32(ws);
        const float4* wsrc = d_wfmt + (size_t)g * (WS_FLOATS / 4);
        for (int q = tid; q < WS_FLOATS / 4; q += NTHREADS)
            cp_async16(ws_s + q * 16, wsrc + q);
        asm volatile("cp.async.commit_group;" ::: "memory");
    }

    // ---- x tile -> smem: row p, layout [p][ks(12)][c(4) as float2 (v_c, v_{c+4})]
    {
        const float* xg = x + (((size_t)b * T_) * G_ + g) * F_;
        for (int q = tid; q < XROWS * 12; q += NTHREADS) {
            int p = q / 12, ksq = q - p * 12;
            int t = tl0 - 1 + p;
            float4 lo = make_float4(0.f, 0.f, 0.f, 0.f), hi = lo;
            if (t >= 0 && t < T_) {
                const float* src = xg + (size_t)t * (G_ * F_) + ksq * 8;
                lo = *(const float4*)(src);
                hi = *(const float4*)(src + 4);
            }
            float* dst = xs + p * XSTRIDE + ksq * 8;
            *(float4*)(dst)     = make_float4(f2tf32f(lo.x), f2tf32f(hi.x), f2tf32f(lo.y), f2tf32f(hi.y));
            *(float4*)(dst + 4) = make_float4(f2tf32f(lo.z), f2tf32f(hi.z), f2tf32f(lo.w), f2tf32f(hi.w));
        }
    }

    // ---- accumulators pre-loaded with bias
    float acc[2][6][4];
    {
        const float* bg = bias + g * O_ + wn * 48 + 2 * lc;
        #pragma unroll
        for (int jn = 0; jn < 6; ++jn) {
            float b0v = bg[jn * 8], b1v = bg[jn * 8 + 1];
            #pragma unroll
            for (int mb = 0; mb < 2; ++mb) {
                acc[mb][jn][0] = b0v; acc[mb][jn][1] = b1v;
                acc[mb][jn][2] = b0v; acc[mb][jn][3] = b1v;
            }
        }
    }

    asm volatile("cp.async.wait_group 0;" ::: "memory");
    __syncthreads();

    // ---- main loop: warp tile m32 x n48, fully unrolled 36 steps
    const float* paw = xs + (wm * 32 + lane4) * XSTRIDE + lc * 2;
    const float* pbl = ws + lane * 12;

    #pragma unroll
    for (int kk = 0; kk < 3; ++kk) {
        #pragma unroll
        for (int ks = 0; ks < 12; ++ks) {
            const float* pbs = pbl + (kk * 12 + ks) * WBLK;
            float4 b0lo = *(const float4*)(pbs + wn * 4);
            float2 b0hi = *(const float2*)(pbs + 8 + wn * 2);
            float4 b1lo = *(const float4*)(pbs + 384 + wn * 4);
            float2 b1hi = *(const float2*)(pbs + 384 + 8 + wn * 2);
            float b0f[6] = { b0lo.x, b0lo.y, b0lo.z, b0lo.w, b0hi.x, b0hi.y };
            float b1f[6] = { b1lo.x, b1lo.y, b1lo.z, b1lo.w, b1hi.x, b1hi.y };

            const float* pam = paw + kk * XSTRIDE + ks * 8;
            float2 alo0 = *(const float2*)(pam);
            float2 ahi0 = *(const float2*)(pam + 8 * XSTRIDE);
            float2 alo1 = *(const float2*)(pam + 16 * XSTRIDE);
            float2 ahi1 = *(const float2*)(pam + 24 * XSTRIDE);

            #pragma unroll
            for (int jn = 0; jn < 6; ++jn) {
                mma_tf32(acc[0][jn], alo0.x, ahi0.x, alo0.y, ahi0.y, b0f[jn], b1f[jn]);
                mma_tf32(acc[1][jn], alo1.x, ahi1.x, alo1.y, ahi1.y, b0f[jn], b1f[jn]);
            }
        }
    }

    // ---- store
    const int colb = wn * 48 + 2 * lc;
    #pragma unroll
    for (int mb = 0; mb < 2; ++mb) {
        int rbase = m0 + wm * 32 + mb * 16 + lane4;
        #pragma unroll
        for (int h = 0; h < 2; ++h) {
            size_t gm = (size_t)(rbase + h * 8);
            float* op = out + (gm * G_ + g) * O_ + colb;
            #pragma unroll
            for (int jn = 0; jn < 6; ++jn)
                *(float2*)(op + jn * 8) = make_float2(acc[mb][jn][2 * h], acc[mb][jn][2 * h + 1]);
        }
    }
}

extern "C" void kernel_launch(void* const* d_in, const int* in_sizes, int n_in,
                              void* d_out, int out_size)
{
    const float* x    = (const float*)d_in[0];
    const float* wgt  = (const float*)d_in[1];
    const float* bias = (const float*)d_in[2];
    float* out        = (float*)d_out;

    cudaFuncSetAttribute(w_reformat_kernel,
                         cudaFuncAttributeMaxDynamicSharedMemorySize, WS_FLOATS * 4);
    cudaFuncSetAttribute(conv1d_mma_kernel,
                         cudaFuncAttributeMaxDynamicSharedMemorySize, SMEM_BYTES);

    w_reformat_kernel<<<G_, 256, WS_FLOATS * 4>>>(wgt);

    dim3 grid((B_ * T_) / MT, G_);   // 8 x 129 = 1032 CTAs
    conv1d_mma_kernel<<<grid, NTHREADS, SMEM_BYTES>>>(x, bias, out);
}

// round 11
// speedup vs baseline: 1.7392x; 1.0691x over previous
#include <cuda_runtime.h>
#include <cstdint>

#define B_  4
#define T_  512
#define G_  129
#define F_  96
#define O_  96

#define HM  128                        // half-window M rows
#define HROWS (HM + 2)                 // 130 with halo
#define XSTRIDE 104                    // 96 data + 8 pad (conflict-free LDS.64)
#define XB_FLOATS (HROWS * XSTRIDE)    // 13520 per buffer

// B layout per (kk,ks) block of 768 floats: [plane b0: 32 slots x 12][plane b1: ...]
#define WBLK 768
#define WS_FLOATS (36 * WBLK)          // 27648
#define SMEM_BYTES ((WS_FLOATS + 2 * XB_FLOATS) * 4)   // 218,752 B

#define NTHREADS 512

__device__ __forceinline__ float f2tf32f(float f) {
    uint32_t r;
    asm("cvt.rna.tf32.f32 %0, %1;" : "=r"(r) : "f"(f));
    return __uint_as_float(r);
}

__device__ __forceinline__ void mma_tf32(float c[4], float a0, float a1, float a2, float a3,
                                         float b0, float b1) {
    asm volatile(
        "mma.sync.aligned.m16n8k8.row.col.f32.tf32.tf32.f32 "
        "{%0,%1,%2,%3}, {%4,%5,%6,%7}, {%8,%9}, {%0,%1,%2,%3};"
        : "+f"(c[0]), "+f"(c[1]), "+f"(c[2]), "+f"(c[3])
        : "r"(__float_as_uint(a0)), "r"(__float_as_uint(a1)),
          "r"(__float_as_uint(a2)), "r"(__float_as_uint(a3)),
          "r"(__float_as_uint(b0)), "r"(__float_as_uint(b1)));
}

__global__ __launch_bounds__(NTHREADS, 1)
void conv1d_mma_kernel(const float* __restrict__ x,
                       const float* __restrict__ w,
                       const float* __restrict__ bias,
                       float* __restrict__ out)
{
    extern __shared__ float sm[];
    float* ws = sm;                                 // 27648 floats (weights, slot layout)
    const int tid = threadIdx.x, wid = tid >> 5, lane = tid & 31;
    const int wg = wid >> 3;                        // warpgroup 0/1
    const int tid2 = tid & 255;                     // thread within WG
    const int wl = wid & 7;                         // warp within WG
    const int wm = wl & 3, wn = wl >> 2;            // 4 M-warps x 2 N-warps
    const int lane4 = lane >> 2, lc = lane & 3;
    const int g = blockIdx.x;

    float* xb = sm + WS_FLOATS + wg * XB_FLOATS;    // this WG's private x buffer

    // ---- W[g] -> smem (tf32, slot layout), once per CTA
    {
        const float4* wg4 = (const float4*)(w + (size_t)g * (O_ * F_ * 3));
        for (int q = tid; q < (O_ * F_ * 3) / 4; q += NTHREADS) {
            float4 v = wg4[q];
            int e = q * 4;
            int o = e / (F_ * 3);
            int rem = e - o * (F_ * 3);              // o fixed across the 4 (288 % 4 == 0)
            int nsub = o & 7, n = o >> 3;
            int slot12 = nsub * 48;
            int pos = (n < 4) ? n : (n < 6 ? n + 4 : (n < 10 ? n - 2 : n));
            const float* vf = (const float*)&v;
            #pragma unroll
            for (int j = 0; j < 4; ++j) {
                int rr = rem + j;
                int f = rr / 3, kk = rr - 3 * f;
                int ks = f >> 3, fp = f & 7;
                int plane = fp >> 2, krow = fp & 3;
                ws[(kk * 12 + ks) * WBLK + plane * 384 + slot12 + krow * 12 + pos] = f2tf32f(vf[j]);
            }
        }
    }

    // ---- bias kept in registers for the whole kernel
    float bias0[6], bias1[6];
    {
        const float* bg = bias + g * O_ + wn * 48 + 2 * lc;
        #pragma unroll
        for (int jn = 0; jn < 6; ++jn) { bias0[jn] = bg[jn * 8]; bias1[jn] = bg[jn * 8 + 1]; }
    }

    __syncthreads();    // weights visible to both WGs; WGs independent from here on

    const float* paw = xb + (wm * 32 + lane4) * XSTRIDE + lc * 2;
    const float* pbl = ws + lane * 12;
    const int barid = wg + 1;

    // ---- 8 half-windows per WG: h = 2*i + wg
    for (int i = 0; i < 8; ++i) {
        const int h = 2 * i + wg;
        const int bb = h >> 2;
        const int t0 = (h & 3) * HM;

        // fill this WG's buffer: 130 halo rows, tf32, paired-c layout
        {
            const float* xgb = x + (((size_t)bb * T_) * G_ + g) * F_;
            for (int q = tid2; q < HROWS * 12; q += 256) {
                int p = q / 12, ksq = q - p * 12;
                int t = t0 - 1 + p;
                float4 lo = make_float4(0.f, 0.f, 0.f, 0.f), hi = lo;
                if (t >= 0 && t < T_) {
                    const float* src = xgb + (size_t)t * (G_ * F_) + ksq * 8;
                    lo = *(const float4*)(src);
                    hi = *(const float4*)(src + 4);
                }
                float* dst = xb + p * XSTRIDE + ksq * 8;
                *(float4*)(dst)     = make_float4(f2tf32f(lo.x), f2tf32f(hi.x), f2tf32f(lo.y), f2tf32f(hi.y));
                *(float4*)(dst + 4) = make_float4(f2tf32f(lo.z), f2tf32f(hi.z), f2tf32f(lo.w), f2tf32f(hi.w));
            }
        }
        asm volatile("bar.sync %0, 256;" :: "r"(barid) : "memory");

        // accumulators from bias
        float acc[2][6][4];
        #pragma unroll
        for (int jn = 0; jn < 6; ++jn) {
            #pragma unroll
            for (int mb = 0; mb < 2; ++mb) {
                acc[mb][jn][0] = bias0[jn]; acc[mb][jn][1] = bias1[jn];
                acc[mb][jn][2] = bias0[jn]; acc[mb][jn][3] = bias1[jn];
            }
        }

        // mainloop: warp tile m32 x n48, fully unrolled 36 steps
        #pragma unroll
        for (int kk = 0; kk < 3; ++kk) {
            #pragma unroll
            for (int ks = 0; ks < 12; ++ks) {
                const float* pbs = pbl + (kk * 12 + ks) * WBLK;
                float4 b0lo = *(const float4*)(pbs + wn * 4);
                float2 b0hi = *(const float2*)(pbs + 8 + wn * 2);
                float4 b1lo = *(const float4*)(pbs + 384 + wn * 4);
                float2 b1hi = *(const float2*)(pbs + 384 + 8 + wn * 2);
                float b0f[6] = { b0lo.x, b0lo.y, b0lo.z, b0lo.w, b0hi.x, b0hi.y };
                float b1f[6] = { b1lo.x, b1lo.y, b1lo.z, b1lo.w, b1hi.x, b1hi.y };

                const float* pam = paw + kk * XSTRIDE + ks * 8;
                float2 alo0 = *(const float2*)(pam);
                float2 ahi0 = *(const float2*)(pam + 8 * XSTRIDE);
                float2 alo1 = *(const float2*)(pam + 16 * XSTRIDE);
                float2 ahi1 = *(const float2*)(pam + 24 * XSTRIDE);

                #pragma unroll
                for (int jn = 0; jn < 6; ++jn) {
                    mma_tf32(acc[0][jn], alo0.x, ahi0.x, alo0.y, ahi0.y, b0f[jn], b1f[jn]);
                    mma_tf32(acc[1][jn], alo1.x, ahi1.x, alo1.y, ahi1.y, b0f[jn], b1f[jn]);
                }
            }
        }

        // store this half-window
        const int colb = wn * 48 + 2 * lc;
        #pragma unroll
        for (int mb = 0; mb < 2; ++mb) {
            int rbase = h * HM + wm * 32 + mb * 16 + lane4;
            #pragma unroll
            for (int hh = 0; hh < 2; ++hh) {
                size_t gm = (size_t)(rbase + hh * 8);
                float* op = out + (gm * G_ + g) * O_ + colb;
                #pragma unroll
                for (int jn = 0; jn < 6; ++jn)
                    *(float2*)(op + jn * 8) = make_float2(acc[mb][jn][2 * hh], acc[mb][jn][2 * hh + 1]);
            }
        }

        // buffer free for next fill only after all 8 warps finished reading
        asm volatile("bar.sync %0, 256;" :: "r"(barid) : "memory");
    }
}

extern "C" void kernel_launch(void* const* d_in, const int* in_sizes, int n_in,
                              void* d_out, int out_size)
{
    const float* x    = (const float*)d_in[0];
    const float* wgt  = (const float*)d_in[1];
    const float* bias = (const float*)d_in[2];
    float* out        = (float*)d_out;

    cudaFuncSetAttribute(conv1d_mma_kernel,
                         cudaFuncAttributeMaxDynamicSharedMemorySize, SMEM_BYTES);

    conv1d_mma_kernel<<<G_, NTHREADS, SMEM_BYTES>>>(x, wgt, bias, out);
}

// round 13
// speedup vs baseline: 2.0628x; 1.1861x over previous
#include <cuda_runtime.h>
#include <cstdint>

#define B_  4
#define T_  512
#define G_  129
#define F_  96
#define O_  96

#define HM  128                        // half-window M rows
#define HROWS (HM + 2)                 // 130 with halo
#define XSTRIDE 100                    // floats: 96 data + 4 pad (bank = (4r+c) mod 32, conflict-free)
#define XB_FLOATS (HROWS * XSTRIDE)    // 13000 per buffer

// B layout per (kk,ks) block of 768 floats: [plane b0: 32 slots x 12][plane b1: ...]
#define WBLK 768
#define WS_FLOATS (36 * WBLK)          // 27648
#define SMEM_BYTES ((WS_FLOATS + 2 * XB_FLOATS) * 4)   // 214,592 B

#define NTHREADS 512

__device__ __forceinline__ float f2tf32f(float f) {
    uint32_t r;
    asm("cvt.rna.tf32.f32 %0, %1;" : "=r"(r) : "f"(f));
    return __uint_as_float(r);
}
__device__ __forceinline__ uint32_t smem_u32(const void* p) {
    uint32_t a;
    asm("{ .reg .u64 t; cvta.to.shared.u64 t, %1; cvt.u32.u64 %0, t; }" : "=r"(a) : "l"(p));
    return a;
}
// 16B async copy with zero-fill when src_sz == 0 (halo rows)
__device__ __forceinline__ void cp_async16z(uint32_t saddr, const void* gptr, uint32_t src_sz) {
    asm volatile("cp.async.cg.shared.global [%0], [%1], 16, %2;"
                 :: "r"(saddr), "l"(gptr), "r"(src_sz));
}

__device__ __forceinline__ void mma_tf32(float c[4], float a0, float a1, float a2, float a3,
                                         float b0, float b1) {
    asm volatile(
        "mma.sync.aligned.m16n8k8.row.col.f32.tf32.tf32.f32 "
        "{%0,%1,%2,%3}, {%4,%5,%6,%7}, {%8,%9}, {%0,%1,%2,%3};"
        : "+f"(c[0]), "+f"(c[1]), "+f"(c[2]), "+f"(c[3])
        : "r"(__float_as_uint(a0)), "r"(__float_as_uint(a1)),
          "r"(__float_as_uint(a2)), "r"(__float_as_uint(a3)),
          "r"(__float_as_uint(b0)), "r"(__float_as_uint(b1)));
}

__global__ __launch_bounds__(NTHREADS, 1)
void conv1d_mma_kernel(const float* __restrict__ x,
                       const float* __restrict__ w,
                       const float* __restrict__ bias,
                       float* __restrict__ out)
{
    extern __shared__ float sm[];
    float* ws = sm;                                 // 27648 floats (weights, slot layout)
    const int tid = threadIdx.x, wid = tid >> 5, lane = tid & 31;
    const int wg = wid >> 3;                        // warpgroup 0/1
    const int tid2 = tid & 255;                     // thread within WG
    const int wl = wid & 7;                         // warp within WG
    const int wm = wl & 3, wn = wl >> 2;            // 4 M-warps x 2 N-warps
    const int lane4 = lane >> 2, lc = lane & 3;
    const int g = blockIdx.x;

    float* xb = sm + WS_FLOATS + wg * XB_FLOATS;    // this WG's private x buffer
    const uint32_t xb_s = smem_u32(xb);

    // ---- W[g] -> smem (tf32 rna, slot layout), once per CTA
    {
        const float4* wg4 = (const float4*)(w + (size_t)g * (O_ * F_ * 3));
        for (int q = tid; q < (O_ * F_ * 3) / 4; q += NTHREADS) {
            float4 v = wg4[q];
            int e = q * 4;
            int o = e / (F_ * 3);
            int rem = e - o * (F_ * 3);              // o fixed across the 4 (288 % 4 == 0)
            int nsub = o & 7, n = o >> 3;
            int slot12 = nsub * 48;
            int pos = (n < 4) ? n : (n < 6 ? n + 4 : (n < 10 ? n - 2 : n));
            const float* vf = (const float*)&v;
            #pragma unroll
            for (int j = 0; j < 4; ++j) {
                int rr = rem + j;
                int f = rr / 3, kk = rr - 3 * f;
                int ks = f >> 3, fp = f & 7;
                int plane = fp >> 2, krow = fp & 3;
                ws[(kk * 12 + ks) * WBLK + plane * 384 + slot12 + krow * 12 + pos] = f2tf32f(vf[j]);
            }
        }
    }

    // ---- bias kept in registers for the whole kernel
    float bias0[6], bias1[6];
    {
        const float* bg = bias + g * O_ + wn * 48 + 2 * lc;
        #pragma unroll
        for (int jn = 0; jn < 6; ++jn) { bias0[jn] = bg[jn * 8]; bias1[jn] = bg[jn * 8 + 1]; }
    }

    __syncthreads();    // weights visible to both WGs; WGs independent from here on

    const float* paw = xb + (wm * 32 + lane4) * XSTRIDE + lc;
    const float* pbl = ws + lane * 12;
    const int barid = wg + 1;

    // ---- 8 half-windows per WG: h = 2*i + wg
    for (int i = 0; i < 8; ++i) {
        const int h = 2 * i + wg;
        const int bb = h >> 2;
        const int t0 = (h & 3) * HM;

        // fill this WG's buffer via cp.async: 130 halo rows x 24 16B-chunks, zero-filled at edges
        {
            const float* xgb = x + (((size_t)bb * T_) * G_ + g) * F_;
            for (int q = tid2; q < HROWS * 24; q += 256) {
                int p = q / 24, c = q - p * 24;
                int t = t0 - 1 + p;
                uint32_t ok = (t >= 0 && t < T_) ? 16u : 0u;
                const float* src = xgb + (size_t)t * (G_ * F_) + c * 4;
                cp_async16z(xb_s + (p * XSTRIDE + c * 4) * 4, src, ok);
            }
            asm volatile("cp.async.commit_group;" ::: "memory");
            asm volatile("cp.async.wait_group 0;" ::: "memory");
        }
        asm volatile("bar.sync %0, 256;" :: "r"(barid) : "memory");

        // accumulators from bias
        float acc[2][6][4];
        #pragma unroll
        for (int jn = 0; jn < 6; ++jn) {
            #pragma unroll
            for (int mb = 0; mb < 2; ++mb) {
                acc[mb][jn][0] = bias0[jn]; acc[mb][jn][1] = bias1[jn];
                acc[mb][jn][2] = bias0[jn]; acc[mb][jn][3] = bias1[jn];
            }
        }

        // mainloop: warp tile m32 x n48, fully unrolled 36 steps; A = raw fp32 (HW tf32 truncation)
        #pragma unroll
        for (int kk = 0; kk < 3; ++kk) {
            #pragma unroll
            for (int ks = 0; ks < 12; ++ks) {
                const float* pbs = pbl + (kk * 12 + ks) * WBLK;
                float4 b0lo = *(const float4*)(pbs + wn * 4);
                float2 b0hi = *(const float2*)(pbs + 8 + wn * 2);
                float4 b1lo = *(const float4*)(pbs + 384 + wn * 4);
                float2 b1hi = *(const float2*)(pbs + 384 + 8 + wn * 2);
                float b0f[6] = { b0lo.x, b0lo.y, b0lo.z, b0lo.w, b0hi.x, b0hi.y };
                float b1f[6] = { b1lo.x, b1lo.y, b1lo.z, b1lo.w, b1hi.x, b1hi.y };

                const float* pam = paw + kk * XSTRIDE + ks * 8;
                float a00 = pam[0];
                float a02 = pam[4];
                float a01 = pam[8 * XSTRIDE];
                float a03 = pam[8 * XSTRIDE + 4];
                float a10 = pam[16 * XSTRIDE];
                float a12 = pam[16 * XSTRIDE + 4];
                float a11 = pam[24 * XSTRIDE];
                float a13 = pam[24 * XSTRIDE + 4];

                #pragma unroll
                for (int jn = 0; jn < 6; ++jn) {
                    mma_tf32(acc[0][jn], a00, a01, a02, a03, b0f[jn], b1f[jn]);
                    mma_tf32(acc[1][jn], a10, a11, a12, a13, b0f[jn], b1f[jn]);
                }
            }
        }

        // store this half-window
        const int colb = wn * 48 + 2 * lc;
        #pragma unroll
        for (int mb = 0; mb < 2; ++mb) {
            int rbase = h * HM + wm * 32 + mb * 16 + lane4;
            #pragma unroll
            for (int hh = 0; hh < 2; ++hh) {
                size_t gm = (size_t)(rbase + hh * 8);
                float* op = out + (gm * G_ + g) * O_ + colb;
                #pragma unroll
                for (int jn = 0; jn < 6; ++jn)
                    *(float2*)(op + jn * 8) = make_float2(acc[mb][jn][2 * hh], acc[mb][jn][2 * hh + 1]);
            }
        }

        // buffer free for next fill only after all 8 warps finished reading
        asm volatile("bar.sync %0, 256;" :: "r"(barid) : "memory");
    }
}

extern "C" void kernel_launch(void* const* d_in, const int* in_sizes, int n_in,
                              void* d_out, int out_size)
{
    const float* x    = (const float*)d_in[0];
    const float* wgt  = (const float*)d_in[1];
    const float* bias = (const float*)d_in[2];
    float* out        = (float*)d_out;

    cudaFuncSetAttribute(conv1d_mma_kernel,
                         cudaFuncAttributeMaxDynamicSharedMemorySize, SMEM_BYTES);

    conv1d_mma_kernel<<<G_, NTHREADS, SMEM_BYTES>>>(x, wgt, bias, out);
}